// round 10
// baseline (speedup 1.0000x reference)
#include <cuda_runtime.h>

#define H 4
#define Dh 64
#define HID 256
#define NGT 100000
#define NUBS 20000
#define NAG 20000
#define ESEEN 320000
#define ENEAR 160000

typedef unsigned long long u64;

__device__ __forceinline__ u64 pk2(float lo, float hi) {
    u64 r; asm("mov.b64 %0,{%1,%2};" : "=l"(r) : "f"(lo), "f"(hi)); return r;
}
__device__ __forceinline__ u64 f2fma(u64 a, u64 b, u64 c) {
    u64 d; asm("fma.rn.f32x2 %0,%1,%2,%3;" : "=l"(d) : "l"(a), "l"(b), "l"(c)); return d;
}
__device__ __forceinline__ float2 upk2(u64 v) {
    float2 r; asm("mov.b64 {%0,%1},%2;" : "=f"(r.x), "=f"(r.y) : "l"(v)); return r;
}
__device__ __forceinline__ void cpa16(unsigned s, const void* g) {
    asm volatile("cp.async.cg.shared.global [%0], [%1], 16;" :: "r"(s), "l"(g));
}

// ---------------- scratch (device globals, no runtime alloc) ----------------
__device__ float g_feat[(NGT + NUBS + 4 * NAG) * HID];
__device__ float g_xcat[NAG * 2 * HID];
__device__ int   g_cnt[2 * NAG];
__device__ int   g_cur[2 * NAG];
__device__ int   g_off[2 * NAG];          // per-dst region start (unordered CSR)
__device__ int   g_base[2];               // per-graph bump counters
__device__ int   g_perm[ESEEN + ENEAR];   // SRC node ids in dst-grouped order

#define FS_SEEN 0L
#define FS_NEAR ((long)NGT * HID)
#define FD_S    ((long)(NGT + NUBS) * HID)
#define RES_S   (FD_S + (long)NAG * HID)
#define FD_N    (RES_S + (long)NAG * HID)
#define RES_N   (FD_N + (long)NAG * HID)

__global__ void k_zero() {
    int i = blockIdx.x * blockDim.x + threadIdx.x;
    if (i < 2 * NAG) g_cnt[i] = 0;
    if (i < 2) g_base[i] = 0;
}

// ---------------- fused projections ----------------
template<int F>
__device__ __forceinline__ void proj_body(const float* __restrict__ x,
                                          const float* __restrict__ W,
                                          const float* __restrict__ b,
                                          int n, long out_off) {
    int node0 = blockIdx.x * 128;
    if (node0 >= n) return;
    __shared__ float sx[128 * 16];
    int cnt = n - node0; if (cnt > 128) cnt = 128;
    int nf4 = (cnt * F) >> 2;
    for (int i = threadIdx.x; i < nf4; i += 256)
        *(float4*)(sx + i * 4) = *(const float4*)(x + (long)node0 * F + i * 4);
    __syncthreads();

    int warp = threadIdx.x >> 5, lane = threadIdx.x & 31;
    int c = (warp & 3) * 64 + (lane << 1);
    int nh = (warp >> 2) * 64;
    u64 wp[F];
#pragma unroll
    for (int k = 0; k < F; k++) wp[k] = *(const u64*)(W + k * HID + c);
    u64 bp = *(const u64*)(b + c);

    int jend = nh + 64; if (jend > cnt) jend = cnt;
#pragma unroll 1
    for (int j = nh; j < jend; j++) {
        const float* xr = sx + j * F;
        u64 acc = bp;
#pragma unroll
        for (int k4 = 0; k4 < F; k4 += 4) {
            float4 xv = *(const float4*)(xr + k4);
            acc = f2fma(pk2(xv.x, xv.x), wp[k4 + 0], acc);
            acc = f2fma(pk2(xv.y, xv.y), wp[k4 + 1], acc);
            acc = f2fma(pk2(xv.z, xv.z), wp[k4 + 2], acc);
            acc = f2fma(pk2(xv.w, xv.w), wp[k4 + 3], acc);
        }
        *(u64*)(g_feat + out_off + (long)(node0 + j) * HID + c) = acc;
    }
}

__global__ void k_proj_all(const float* xg, const float* xu, const float* xa,
                           const float* Wsg, const float* bsg,
                           const float* Wsu, const float* bsu,
                           const float* W0, const float* b0,
                           const float* W1, const float* b1,
                           const float* W2, const float* b2,
                           const float* W3, const float* b3,
                           int n_gt, int n_ubs, int n_ag) {
    switch (blockIdx.y) {
        case 0: proj_body<8>(xg, Wsg, bsg, n_gt, FS_SEEN); break;
        case 1: proj_body<8>(xu, Wsu, bsu, n_ubs, FS_NEAR); break;
        case 2: proj_body<16>(xa, W0, b0, n_ag, FD_S);  break;
        case 3: proj_body<16>(xa, W1, b1, n_ag, RES_S); break;
        case 4: proj_body<16>(xa, W2, b2, n_ag, FD_N);  break;
        default: proj_body<16>(xa, W3, b3, n_ag, RES_N); break;
    }
}

// ---------------- CSR build ----------------
__global__ void k_hist(const int* __restrict__ dA, int eA,
                       const int* __restrict__ dB, int eB) {
    int g = blockIdx.y;
    const int* dst = g ? dB : dA;
    int e = g ? eB : eA;
    int co = g ? NAG : 0;
    for (int i = blockIdx.x * blockDim.x + threadIdx.x; i < e;
         i += gridDim.x * blockDim.x)
        atomicAdd(&g_cnt[co + __ldg(dst + i)], 1);
}

// warp-aggregated unordered offset assignment
__global__ void k_assign(int n) {
    int i = blockIdx.x * blockDim.x + threadIdx.x;
    if (i >= 2 * n) return;
    int g = (i >= n) ? 1 : 0;
    int lane = threadIdx.x & 31;
    int c = g_cnt[i];
    int pre = c;
#pragma unroll
    for (int o = 1; o < 32; o <<= 1) {
        int v = __shfl_up_sync(0xffffffffu, pre, o);
        if (lane >= o) pre += v;
    }
    int total = __shfl_sync(0xffffffffu, pre, 31);
    int excl = pre - c;
    int base = 0;
    if (lane == 31) base = atomicAdd(&g_base[g], total);
    base = __shfl_sync(0xffffffffu, base, 31);
    g_off[i] = base + excl;
    g_cur[i] = base + excl;
}

__global__ void k_scatter(const int* __restrict__ dA, const int* __restrict__ sA, int eA,
                          const int* __restrict__ dB, const int* __restrict__ sB, int eB) {
    int g = blockIdx.y;
    const int* dst = g ? dB : dA;
    const int* src = g ? sB : sA;
    int e = g ? eB : eA;
    int pb = g ? ESEEN : 0;
    for (int i = blockIdx.x * blockDim.x + threadIdx.x; i < e;
         i += gridDim.x * blockDim.x) {
        int p = atomicAdd(&g_cur[g * NAG + __ldg(dst + i)], 1);
        g_perm[pb + p] = __ldg(src + i);
    }
}

// ---------------- GATv2: one warp per dst, all 4 heads ----------------
// cp.async double-buffered smem pipeline: prefetch state lives in SMEM, not regs.
__device__ __forceinline__ float lrelu(float v) { return (v >= 0.f) ? v : 0.2f * v; }

__device__ __forceinline__ float escore(float4 fa, float4 fb, float4 d0, float4 d1,
                                        float4 a0, float4 a1) {
    float p;
    p = lrelu(fa.x + d0.x) * a0.x;
    p = fmaf(lrelu(fa.y + d0.y), a0.y, p);
    p = fmaf(lrelu(fa.z + d0.z), a0.z, p);
    p = fmaf(lrelu(fa.w + d0.w), a0.w, p);
    p = fmaf(lrelu(fb.x + d1.x), a1.x, p);
    p = fmaf(lrelu(fb.y + d1.y), a1.y, p);
    p = fmaf(lrelu(fb.z + d1.z), a1.z, p);
    p = fmaf(lrelu(fb.w + d1.w), a1.w, p);
    return p;
}

#define GAT_WARPS 4

__global__ void __launch_bounds__(32 * GAT_WARPS) k_gat(const float* __restrict__ attnS,
                                                        const float* __restrict__ attnN,
                                                        int nag) {
    // per-warp: 2 stages x 4 rows x 256 floats = 8KB; block total 32KB
    __shared__ float sbuf[GAT_WARPS][2][4][256];

    int g = blockIdx.y;
    const float* attn = g ? attnN : attnS;
    long fs_off  = g ? FS_NEAR : FS_SEEN;
    long fd_off  = g ? FD_N    : FD_S;
    long res_off = g ? RES_N   : RES_S;
    int gbase    = g ? NAG : 0;
    int pb       = g ? ESEEN : 0;
    int xoff     = g ? HID : 0;

    int warp = threadIdx.x >> 5, lane = threadIdx.x & 31;
    int dstn = blockIdx.x * GAT_WARPS + warp;
    if (dstn >= nag) return;
    int off = lane * 8;

    float4 a0 = __ldg((const float4*)(attn + off));
    float4 a1 = __ldg((const float4*)(attn + off + 4));
    const float* fdr = g_feat + fd_off + (long)dstn * HID + off;
    float4 d0 = *(const float4*)(fdr);
    float4 d1 = *(const float4*)(fdr + 4);

    int e0 = g_off[gbase + dstn];
    int e1 = e0 + g_cnt[gbase + dstn];
    const float* fs = g_feat + fs_off;
    const int* pp = g_perm + pb;

    float mx = -3.0e38f, den = 0.f;
    float4 acc0 = make_float4(0.f, 0.f, 0.f, 0.f), acc1 = acc0;

    if (e0 < e1) {
        unsigned swb = (unsigned)__cvta_generic_to_shared(&sbuf[warp][0][0][0]);
        int ids[4], nids[4];
        auto ldids = [&](int j, int* out) {
            int rr = e1 - j;
            out[0] = pp[j];
            out[1] = (rr > 1) ? pp[j + 1] : out[0];
            out[2] = (rr > 2) ? pp[j + 2] : out[0];
            out[3] = (rr > 3) ? pp[j + 3] : out[0];
        };
        // lane copies exactly the 32B it later reads: lo 16B at [lane*16],
        // hi 16B at [+512B] -> own-thread visibility, conflict-free LDS.128.
        auto issue = [&](int stage, const int* id) {
            unsigned sb = swb + stage * 4096 + lane * 16;
#pragma unroll
            for (int k = 0; k < 4; k++) {
                const float* src = fs + (long)id[k] * HID + off;
                cpa16(sb + k * 1024, src);
                cpa16(sb + k * 1024 + 512, src + 4);
            }
        };

        ldids(e0, ids);
        issue(0, ids);
        asm volatile("cp.async.commit_group;");
        bool have_next = (e0 + 4 < e1);
        if (have_next) ldids(e0 + 4, nids);
        int stage = 0;

        for (int i = e0; i < e1; i += 4) {
            if (have_next) {
                issue(stage ^ 1, nids);
                asm volatile("cp.async.commit_group;");
                asm volatile("cp.async.wait_group 1;");
            } else {
                asm volatile("cp.async.wait_group 0;");
            }
            bool have_next2 = (i + 8 < e1);
            if (have_next2) ldids(i + 8, nids);

            const float* sp = &sbuf[warp][stage][0][0];
            float4 fa[4], fb[4];
#pragma unroll
            for (int k = 0; k < 4; k++) {
                fa[k] = *(const float4*)(sp + k * 256 + lane * 4);
                fb[k] = *(const float4*)(sp + k * 256 + 128 + lane * 4);
            }

            float p0 = escore(fa[0], fb[0], d0, d1, a0, a1);
            float p1 = escore(fa[1], fb[1], d0, d1, a0, a1);
            float p2 = escore(fa[2], fb[2], d0, d1, a0, a1);
            float p3 = escore(fa[3], fb[3], d0, d1, a0, a1);
#pragma unroll
            for (int o = 1; o < 8; o <<= 1) {
                p0 += __shfl_xor_sync(0xffffffffu, p0, o);
                p1 += __shfl_xor_sync(0xffffffffu, p1, o);
                p2 += __shfl_xor_sync(0xffffffffu, p2, o);
                p3 += __shfl_xor_sync(0xffffffffu, p3, o);
            }
            int r = e1 - i;
            if (r < 2) p1 = -3.0e38f;
            if (r < 3) p2 = -3.0e38f;
            if (r < 4) p3 = -3.0e38f;

            float cm = fmaxf(fmaxf(p0, p1), fmaxf(p2, p3));
            float nmx = fmaxf(mx, cm);
            float scale = __expf(mx - nmx);
            float x0 = __expf(p0 - nmx);
            float x1 = __expf(p1 - nmx);
            float x2 = __expf(p2 - nmx);
            float x3 = __expf(p3 - nmx);
            den = fmaf(den, scale, (x0 + x1) + (x2 + x3));
            acc0.x = fmaf(acc0.x, scale, fmaf(x0, fa[0].x, fmaf(x1, fa[1].x, fmaf(x2, fa[2].x, x3 * fa[3].x))));
            acc0.y = fmaf(acc0.y, scale, fmaf(x0, fa[0].y, fmaf(x1, fa[1].y, fmaf(x2, fa[2].y, x3 * fa[3].y))));
            acc0.z = fmaf(acc0.z, scale, fmaf(x0, fa[0].z, fmaf(x1, fa[1].z, fmaf(x2, fa[2].z, x3 * fa[3].z))));
            acc0.w = fmaf(acc0.w, scale, fmaf(x0, fa[0].w, fmaf(x1, fa[1].w, fmaf(x2, fa[2].w, x3 * fa[3].w))));
            acc1.x = fmaf(acc1.x, scale, fmaf(x0, fb[0].x, fmaf(x1, fb[1].x, fmaf(x2, fb[2].x, x3 * fb[3].x))));
            acc1.y = fmaf(acc1.y, scale, fmaf(x0, fb[0].y, fmaf(x1, fb[1].y, fmaf(x2, fb[2].y, x3 * fb[3].y))));
            acc1.z = fmaf(acc1.z, scale, fmaf(x0, fb[0].z, fmaf(x1, fb[1].z, fmaf(x2, fb[2].z, x3 * fb[3].z))));
            acc1.w = fmaf(acc1.w, scale, fmaf(x0, fb[0].w, fmaf(x1, fb[1].w, fmaf(x2, fb[2].w, x3 * fb[3].w))));
            mx = nmx;
            stage ^= 1;
            have_next = have_next2;
        }
    }

    const float* rvr = g_feat + res_off + (long)dstn * HID + off;
    float4 r0 = *(const float4*)(rvr);
    float4 r1 = *(const float4*)(rvr + 4);
    float inv = (e1 == e0) ? 1.f : (1.f / den);
    float4 o0, o1;
    o0.x = fmaxf(fmaf(acc0.x, inv, r0.x), 0.f);
    o0.y = fmaxf(fmaf(acc0.y, inv, r0.y), 0.f);
    o0.z = fmaxf(fmaf(acc0.z, inv, r0.z), 0.f);
    o0.w = fmaxf(fmaf(acc0.w, inv, r0.w), 0.f);
    o1.x = fmaxf(fmaf(acc1.x, inv, r1.x), 0.f);
    o1.y = fmaxf(fmaf(acc1.y, inv, r1.y), 0.f);
    o1.z = fmaxf(fmaf(acc1.z, inv, r1.z), 0.f);
    o1.w = fmaxf(fmaf(acc1.w, inv, r1.w), 0.f);
    float* ox = g_xcat + (long)dstn * (2 * HID) + xoff + off;
    *(float4*)(ox) = o0;
    *(float4*)(ox + 4) = o1;
}

// ---------------- final GEMM: out = relu(xcat[M,512] @ W[512,256] + b) ----------------
__global__ void __launch_bounds__(256) k_gemm(const float* __restrict__ B,
                                              const float* __restrict__ bias,
                                              float* __restrict__ C, int M) {
    const int K = 2 * HID, N = HID;
    __shared__ float sA[16][68];
    __shared__ float sB[16][128];
    int bm = blockIdx.y * 64, bn = blockIdx.x * 128;
    int tx = threadIdx.x & 15, ty = threadIdx.x >> 4;
    u64 acc[4][4] = {};
    for (int k0 = 0; k0 < K; k0 += 16) {
        {
            int m = threadIdx.x >> 2, k4 = (threadIdx.x & 3) * 4;
            int gm = bm + m;
            float4 v = (gm < M) ? *(const float4*)(g_xcat + (long)gm * K + k0 + k4)
                                : make_float4(0.f, 0.f, 0.f, 0.f);
            sA[k4 + 0][m] = v.x; sA[k4 + 1][m] = v.y;
            sA[k4 + 2][m] = v.z; sA[k4 + 3][m] = v.w;
        }
#pragma unroll
        for (int t = 0; t < 2; t++) {
            int idx = threadIdx.x + t * 256;
            int k = idx >> 5, n4 = (idx & 31) * 4;
            *(float4*)(&sB[k][n4]) = *(const float4*)(B + (long)(k0 + k) * N + bn + n4);
        }
        __syncthreads();
#pragma unroll
        for (int k = 0; k < 16; k++) {
            float ar[4];
            *(float4*)(ar) = *(const float4*)(&sA[k][ty * 4]);
            ulonglong2 b01 = *(const ulonglong2*)(&sB[k][tx * 4]);
            ulonglong2 b23 = *(const ulonglong2*)(&sB[k][64 + tx * 4]);
            u64 bp[4] = { b01.x, b01.y, b23.x, b23.y };
#pragma unroll
            for (int i = 0; i < 4; i++) {
                u64 ap = pk2(ar[i], ar[i]);
#pragma unroll
                for (int jp = 0; jp < 4; jp++)
                    acc[i][jp] = f2fma(ap, bp[jp], acc[i][jp]);
            }
        }
        __syncthreads();
    }
#pragma unroll
    for (int i = 0; i < 4; i++) {
        int m = bm + ty * 4 + i;
        if (m >= M) continue;
#pragma unroll
        for (int jp = 0; jp < 4; jp++) {
            int n = bn + ((jp < 2) ? (tx * 4 + jp * 2) : (64 + tx * 4 + (jp - 2) * 2));
            float2 v = upk2(acc[i][jp]);
            v.x = fmaxf(v.x + bias[n], 0.f);
            v.y = fmaxf(v.y + bias[n + 1], 0.f);
            *(float2*)(C + (long)m * N + n) = v;
        }
    }
}

// ---------------- launch ----------------
extern "C" void kernel_launch(void* const* d_in, const int* in_sizes, int n_in,
                              void* d_out, int out_size) {
    const float* x_gt   = (const float*)d_in[0];
    const float* x_ubs  = (const float*)d_in[1];
    const float* x_ag   = (const float*)d_in[2];
    const int* seen_src = (const int*)d_in[3];
    const int* seen_dst = (const int*)d_in[4];
    const int* near_src = (const int*)d_in[5];
    const int* near_dst = (const int*)d_in[6];
    const float* Ws_seen = (const float*)d_in[7];
    const float* bs_seen = (const float*)d_in[8];
    const float* Wd_seen = (const float*)d_in[9];
    const float* bd_seen = (const float*)d_in[10];
    const float* attn_seen = (const float*)d_in[11];
    const float* Wr_seen = (const float*)d_in[12];
    const float* br_seen = (const float*)d_in[13];
    const float* Ws_near = (const float*)d_in[14];
    const float* bs_near = (const float*)d_in[15];
    const float* Wd_near = (const float*)d_in[16];
    const float* bd_near = (const float*)d_in[17];
    const float* attn_near = (const float*)d_in[18];
    const float* Wr_near = (const float*)d_in[19];
    const float* br_near = (const float*)d_in[20];
    const float* W_aggr  = (const float*)d_in[21];
    const float* b_aggr  = (const float*)d_in[22];
    float* out = (float*)d_out;

    int n_gt  = in_sizes[0] / 8;
    int n_ubs = in_sizes[1] / 8;
    int n_ag  = in_sizes[2] / 16;
    int e_seen = in_sizes[3];
    int e_near = in_sizes[5];

    k_zero<<<(2 * NAG + 255) / 256, 256>>>();

    int pbx = (n_gt + 127) / 128;
    k_proj_all<<<dim3(pbx, 6), 256>>>(x_gt, x_ubs, x_ag,
        Ws_seen, bs_seen, Ws_near, bs_near,
        Wd_seen, bd_seen, Wr_seen, br_seen,
        Wd_near, bd_near, Wr_near, br_near,
        n_gt, n_ubs, n_ag);

    k_hist<<<dim3(256, 2), 256>>>(seen_dst, e_seen, near_dst, e_near);
    k_assign<<<(2 * n_ag + 255) / 256, 256>>>(n_ag);
    k_scatter<<<dim3(256, 2), 256>>>(seen_dst, seen_src, e_seen,
                                     near_dst, near_src, e_near);

    k_gat<<<dim3((n_ag + GAT_WARPS - 1) / GAT_WARPS, 2), 32 * GAT_WARPS>>>(
        attn_seen, attn_near, n_ag);

    k_gemm<<<dim3(HID / 128, (n_ag + 63) / 64), 256>>>(W_aggr, b_aggr, out, n_ag);
}

// round 11
// speedup vs baseline: 1.2046x; 1.2046x over previous
#include <cuda_runtime.h>

#define H 4
#define Dh 64
#define HID 256
#define NGT 100000
#define NUBS 20000
#define NAG 20000
#define ESEEN 320000
#define ENEAR 160000

typedef unsigned long long u64;

__device__ __forceinline__ u64 pk2(float lo, float hi) {
    u64 r; asm("mov.b64 %0,{%1,%2};" : "=l"(r) : "f"(lo), "f"(hi)); return r;
}
__device__ __forceinline__ u64 f2fma(u64 a, u64 b, u64 c) {
    u64 d; asm("fma.rn.f32x2 %0,%1,%2,%3;" : "=l"(d) : "l"(a), "l"(b), "l"(c)); return d;
}
__device__ __forceinline__ float2 upk2(u64 v) {
    float2 r; asm("mov.b64 {%0,%1},%2;" : "=f"(r.x), "=f"(r.y) : "l"(v)); return r;
}

// ---------------- scratch (device globals, no runtime alloc) ----------------
__device__ float g_feat[(NGT + NUBS + 4 * NAG) * HID];
__device__ float g_xcat[NAG * 2 * HID];
__device__ int   g_cnt[2 * NAG];
__device__ int   g_cur[2 * NAG];
__device__ int   g_off[2 * NAG];          // per-dst region start (unordered CSR)
__device__ int   g_base[2];               // per-graph bump counters
__device__ int   g_perm[ESEEN + ENEAR];   // SRC node ids in dst-grouped order

#define FS_SEEN 0L
#define FS_NEAR ((long)NGT * HID)
#define FD_S    ((long)(NGT + NUBS) * HID)
#define RES_S   (FD_S + (long)NAG * HID)
#define FD_N    (RES_S + (long)NAG * HID)
#define RES_N   (FD_N + (long)NAG * HID)

__global__ void k_zero() {
    int i = blockIdx.x * blockDim.x + threadIdx.x;
    if (i < 2 * NAG) g_cnt[i] = 0;
    if (i < 2) g_base[i] = 0;
}

// ---------------- fused projections ----------------
template<int F>
__device__ __forceinline__ void proj_body(const float* __restrict__ x,
                                          const float* __restrict__ W,
                                          const float* __restrict__ b,
                                          int n, long out_off) {
    int node0 = blockIdx.x * 128;
    if (node0 >= n) return;
    __shared__ float sx[128 * 16];
    int cnt = n - node0; if (cnt > 128) cnt = 128;
    int nf4 = (cnt * F) >> 2;
    for (int i = threadIdx.x; i < nf4; i += 256)
        *(float4*)(sx + i * 4) = *(const float4*)(x + (long)node0 * F + i * 4);
    __syncthreads();

    int warp = threadIdx.x >> 5, lane = threadIdx.x & 31;
    int c = (warp & 3) * 64 + (lane << 1);
    int nh = (warp >> 2) * 64;
    u64 wp[F];
#pragma unroll
    for (int k = 0; k < F; k++) wp[k] = *(const u64*)(W + k * HID + c);
    u64 bp = *(const u64*)(b + c);

    int jend = nh + 64; if (jend > cnt) jend = cnt;
#pragma unroll 1
    for (int j = nh; j < jend; j++) {
        const float* xr = sx + j * F;
        u64 acc = bp;
#pragma unroll
        for (int k4 = 0; k4 < F; k4 += 4) {
            float4 xv = *(const float4*)(xr + k4);
            acc = f2fma(pk2(xv.x, xv.x), wp[k4 + 0], acc);
            acc = f2fma(pk2(xv.y, xv.y), wp[k4 + 1], acc);
            acc = f2fma(pk2(xv.z, xv.z), wp[k4 + 2], acc);
            acc = f2fma(pk2(xv.w, xv.w), wp[k4 + 3], acc);
        }
        *(u64*)(g_feat + out_off + (long)(node0 + j) * HID + c) = acc;
    }
}

__global__ void k_proj_all(const float* xg, const float* xu, const float* xa,
                           const float* Wsg, const float* bsg,
                           const float* Wsu, const float* bsu,
                           const float* W0, const float* b0,
                           const float* W1, const float* b1,
                           const float* W2, const float* b2,
                           const float* W3, const float* b3,
                           int n_gt, int n_ubs, int n_ag) {
    switch (blockIdx.y) {
        case 0: proj_body<8>(xg, Wsg, bsg, n_gt, FS_SEEN); break;
        case 1: proj_body<8>(xu, Wsu, bsu, n_ubs, FS_NEAR); break;
        case 2: proj_body<16>(xa, W0, b0, n_ag, FD_S);  break;
        case 3: proj_body<16>(xa, W1, b1, n_ag, RES_S); break;
        case 4: proj_body<16>(xa, W2, b2, n_ag, FD_N);  break;
        default: proj_body<16>(xa, W3, b3, n_ag, RES_N); break;
    }
}

// ---------------- CSR build ----------------
__global__ void k_hist(const int* __restrict__ dA, int eA,
                       const int* __restrict__ dB, int eB) {
    int g = blockIdx.y;
    const int* dst = g ? dB : dA;
    int e = g ? eB : eA;
    int co = g ? NAG : 0;
    for (int i = blockIdx.x * blockDim.x + threadIdx.x; i < e;
         i += gridDim.x * blockDim.x)
        atomicAdd(&g_cnt[co + __ldg(dst + i)], 1);
}

// warp-aggregated unordered offset assignment
__global__ void k_assign(int n) {
    int i = blockIdx.x * blockDim.x + threadIdx.x;
    if (i >= 2 * n) return;
    int g = (i >= n) ? 1 : 0;
    int lane = threadIdx.x & 31;
    int c = g_cnt[i];
    int pre = c;
#pragma unroll
    for (int o = 1; o < 32; o <<= 1) {
        int v = __shfl_up_sync(0xffffffffu, pre, o);
        if (lane >= o) pre += v;
    }
    int total = __shfl_sync(0xffffffffu, pre, 31);
    int excl = pre - c;
    int base = 0;
    if (lane == 31) base = atomicAdd(&g_base[g], total);
    base = __shfl_sync(0xffffffffu, base, 31);
    g_off[i] = base + excl;
    g_cur[i] = base + excl;
}

__global__ void k_scatter(const int* __restrict__ dA, const int* __restrict__ sA, int eA,
                          const int* __restrict__ dB, const int* __restrict__ sB, int eB) {
    int g = blockIdx.y;
    const int* dst = g ? dB : dA;
    const int* src = g ? sB : sA;
    int e = g ? eB : eA;
    int pb = g ? ESEEN : 0;
    for (int i = blockIdx.x * blockDim.x + threadIdx.x; i < e;
         i += gridDim.x * blockDim.x) {
        int p = atomicAdd(&g_cur[g * NAG + __ldg(dst + i)], 1);
        g_perm[pb + p] = __ldg(src + i);
    }
}

// ---------------- GATv2: one warp per dst, all 4 heads; chunk-of-4 (r7 form) ----
__device__ __forceinline__ float lrelu(float v) { return (v >= 0.f) ? v : 0.2f * v; }

__device__ __forceinline__ float escore(float4 fa, float4 fb, float4 d0, float4 d1,
                                        float4 a0, float4 a1) {
    float p;
    p = lrelu(fa.x + d0.x) * a0.x;
    p = fmaf(lrelu(fa.y + d0.y), a0.y, p);
    p = fmaf(lrelu(fa.z + d0.z), a0.z, p);
    p = fmaf(lrelu(fa.w + d0.w), a0.w, p);
    p = fmaf(lrelu(fb.x + d1.x), a1.x, p);
    p = fmaf(lrelu(fb.y + d1.y), a1.y, p);
    p = fmaf(lrelu(fb.z + d1.z), a1.z, p);
    p = fmaf(lrelu(fb.w + d1.w), a1.w, p);
    return p;
}

__global__ void __launch_bounds__(256) k_gat(const float* __restrict__ attnS,
                                             const float* __restrict__ attnN, int nag) {
    int g = blockIdx.y;
    const float* attn = g ? attnN : attnS;
    long fs_off  = g ? FS_NEAR : FS_SEEN;
    long fd_off  = g ? FD_N    : FD_S;
    long res_off = g ? RES_N   : RES_S;
    int gbase    = g ? NAG : 0;
    int pb       = g ? ESEEN : 0;
    int xoff     = g ? HID : 0;

    int warp = threadIdx.x >> 5, lane = threadIdx.x & 31;
    int dstn = blockIdx.x * 8 + warp;
    if (dstn >= nag) return;
    int off = lane * 8;

    float4 a0 = __ldg((const float4*)(attn + off));
    float4 a1 = __ldg((const float4*)(attn + off + 4));
    const float* fdr = g_feat + fd_off + (long)dstn * HID + off;
    float4 d0 = *(const float4*)(fdr);
    float4 d1 = *(const float4*)(fdr + 4);
    const float* rvr = g_feat + res_off + (long)dstn * HID + off;
    float4 r0 = *(const float4*)(rvr);
    float4 r1 = *(const float4*)(rvr + 4);

    int e0 = g_off[gbase + dstn];
    int e1 = e0 + g_cnt[gbase + dstn];
    const float* fs = g_feat + fs_off;
    const int* pp = g_perm + pb;

    int id0 = 0, id1 = 0, id2 = 0, id3 = 0;
    if (e0 < e1) {
        int rr = e1 - e0;
        id0 = pp[e0];
        id1 = (rr > 1) ? pp[e0 + 1] : id0;
        id2 = (rr > 2) ? pp[e0 + 2] : id0;
        id3 = (rr > 3) ? pp[e0 + 3] : id0;
    }

    float mx = -3.0e38f, den = 0.f;
    float4 acc0 = make_float4(0.f, 0.f, 0.f, 0.f), acc1 = acc0;

    for (int i = e0; i < e1; i += 4) {
        const float* p0r = fs + (long)id0 * HID + off;
        const float* p1r = fs + (long)id1 * HID + off;
        const float* p2r = fs + (long)id2 * HID + off;
        const float* p3r = fs + (long)id3 * HID + off;
        float4 f0a = __ldg((const float4*)p0r), f0b = __ldg((const float4*)(p0r + 4));
        float4 f1a = __ldg((const float4*)p1r), f1b = __ldg((const float4*)(p1r + 4));
        float4 f2a = __ldg((const float4*)p2r), f2b = __ldg((const float4*)(p2r + 4));
        float4 f3a = __ldg((const float4*)p3r), f3b = __ldg((const float4*)(p3r + 4));

        // prefetch next chunk's ids while gathers are in flight
        if (i + 4 < e1) {
            int j = i + 4, rr = e1 - j;
            id0 = pp[j];
            id1 = (rr > 1) ? pp[j + 1] : id0;
            id2 = (rr > 2) ? pp[j + 2] : id0;
            id3 = (rr > 3) ? pp[j + 3] : id0;
        }

        float p0 = escore(f0a, f0b, d0, d1, a0, a1);
        float p1 = escore(f1a, f1b, d0, d1, a0, a1);
        float p2 = escore(f2a, f2b, d0, d1, a0, a1);
        float p3 = escore(f3a, f3b, d0, d1, a0, a1);
        // segmented sum over the 8 lanes of each head
#pragma unroll
        for (int o = 1; o < 8; o <<= 1) {
            p0 += __shfl_xor_sync(0xffffffffu, p0, o);
            p1 += __shfl_xor_sync(0xffffffffu, p1, o);
            p2 += __shfl_xor_sync(0xffffffffu, p2, o);
            p3 += __shfl_xor_sync(0xffffffffu, p3, o);
        }
        int r = e1 - i;
        if (r < 2) p1 = -3.0e38f;
        if (r < 3) p2 = -3.0e38f;
        if (r < 4) p3 = -3.0e38f;

        float cm = fmaxf(fmaxf(p0, p1), fmaxf(p2, p3));
        float nmx = fmaxf(mx, cm);
        float scale = __expf(mx - nmx);
        float x0 = __expf(p0 - nmx);
        float x1 = __expf(p1 - nmx);
        float x2 = __expf(p2 - nmx);
        float x3 = __expf(p3 - nmx);
        den = fmaf(den, scale, (x0 + x1) + (x2 + x3));
        acc0.x = fmaf(acc0.x, scale, fmaf(x0, f0a.x, fmaf(x1, f1a.x, fmaf(x2, f2a.x, x3 * f3a.x))));
        acc0.y = fmaf(acc0.y, scale, fmaf(x0, f0a.y, fmaf(x1, f1a.y, fmaf(x2, f2a.y, x3 * f3a.y))));
        acc0.z = fmaf(acc0.z, scale, fmaf(x0, f0a.z, fmaf(x1, f1a.z, fmaf(x2, f2a.z, x3 * f3a.z))));
        acc0.w = fmaf(acc0.w, scale, fmaf(x0, f0a.w, fmaf(x1, f1a.w, fmaf(x2, f2a.w, x3 * f3a.w))));
        acc1.x = fmaf(acc1.x, scale, fmaf(x0, f0b.x, fmaf(x1, f1b.x, fmaf(x2, f2b.x, x3 * f3b.x))));
        acc1.y = fmaf(acc1.y, scale, fmaf(x0, f0b.y, fmaf(x1, f1b.y, fmaf(x2, f2b.y, x3 * f3b.y))));
        acc1.z = fmaf(acc1.z, scale, fmaf(x0, f0b.z, fmaf(x1, f1b.z, fmaf(x2, f2b.z, x3 * f3b.z))));
        acc1.w = fmaf(acc1.w, scale, fmaf(x0, f0b.w, fmaf(x1, f1b.w, fmaf(x2, f2b.w, x3 * f3b.w))));
        mx = nmx;
    }
    float inv = (e1 == e0) ? 1.f : (1.f / den);
    float4 o0, o1;
    o0.x = fmaxf(fmaf(acc0.x, inv, r0.x), 0.f);
    o0.y = fmaxf(fmaf(acc0.y, inv, r0.y), 0.f);
    o0.z = fmaxf(fmaf(acc0.z, inv, r0.z), 0.f);
    o0.w = fmaxf(fmaf(acc0.w, inv, r0.w), 0.f);
    o1.x = fmaxf(fmaf(acc1.x, inv, r1.x), 0.f);
    o1.y = fmaxf(fmaf(acc1.y, inv, r1.y), 0.f);
    o1.z = fmaxf(fmaf(acc1.z, inv, r1.z), 0.f);
    o1.w = fmaxf(fmaf(acc1.w, inv, r1.w), 0.f);
    float* ox = g_xcat + (long)dstn * (2 * HID) + xoff + off;
    *(float4*)(ox) = o0;
    *(float4*)(ox + 4) = o1;
}

// ---------------- final GEMM: out = relu(xcat[M,512] @ W[512,256] + b) ----------------
// 64x128 tile, 256 threads, 4x8 microtile, f32x2 FMA.
__global__ void __launch_bounds__(256) k_gemm(const float* __restrict__ B,
                                              const float* __restrict__ bias,
                                              float* __restrict__ C, int M) {
    const int K = 2 * HID, N = HID;
    __shared__ float sA[16][68];
    __shared__ float sB[16][128];
    int bm = blockIdx.y * 64, bn = blockIdx.x * 128;
    int tx = threadIdx.x & 15, ty = threadIdx.x >> 4;
    u64 acc[4][4] = {};
    for (int k0 = 0; k0 < K; k0 += 16) {
        {
            int m = threadIdx.x >> 2, k4 = (threadIdx.x & 3) * 4;
            int gm = bm + m;
            float4 v = (gm < M) ? *(const float4*)(g_xcat + (long)gm * K + k0 + k4)
                                : make_float4(0.f, 0.f, 0.f, 0.f);
            sA[k4 + 0][m] = v.x; sA[k4 + 1][m] = v.y;
            sA[k4 + 2][m] = v.z; sA[k4 + 3][m] = v.w;
        }
#pragma unroll
        for (int t = 0; t < 2; t++) {
            int idx = threadIdx.x + t * 256;
            int k = idx >> 5, n4 = (idx & 31) * 4;
            *(float4*)(&sB[k][n4]) = *(const float4*)(B + (long)(k0 + k) * N + bn + n4);
        }
        __syncthreads();
#pragma unroll
        for (int k = 0; k < 16; k++) {
            float ar[4];
            *(float4*)(ar) = *(const float4*)(&sA[k][ty * 4]);
            ulonglong2 b01 = *(const ulonglong2*)(&sB[k][tx * 4]);
            ulonglong2 b23 = *(const ulonglong2*)(&sB[k][64 + tx * 4]);
            u64 bp[4] = { b01.x, b01.y, b23.x, b23.y };
#pragma unroll
            for (int i = 0; i < 4; i++) {
                u64 ap = pk2(ar[i], ar[i]);
#pragma unroll
                for (int jp = 0; jp < 4; jp++)
                    acc[i][jp] = f2fma(ap, bp[jp], acc[i][jp]);
            }
        }
        __syncthreads();
    }
#pragma unroll
    for (int i = 0; i < 4; i++) {
        int m = bm + ty * 4 + i;
        if (m >= M) continue;
#pragma unroll
        for (int jp = 0; jp < 4; jp++) {
            int n = bn + ((jp < 2) ? (tx * 4 + jp * 2) : (64 + tx * 4 + (jp - 2) * 2));
            float2 v = upk2(acc[i][jp]);
            v.x = fmaxf(v.x + bias[n], 0.f);
            v.y = fmaxf(v.y + bias[n + 1], 0.f);
            *(float2*)(C + (long)m * N + n) = v;
        }
    }
}

// ---------------- launch ----------------
extern "C" void kernel_launch(void* const* d_in, const int* in_sizes, int n_in,
                              void* d_out, int out_size) {
    const float* x_gt   = (const float*)d_in[0];
    const float* x_ubs  = (const float*)d_in[1];
    const float* x_ag   = (const float*)d_in[2];
    const int* seen_src = (const int*)d_in[3];
    const int* seen_dst = (const int*)d_in[4];
    const int* near_src = (const int*)d_in[5];
    const int* near_dst = (const int*)d_in[6];
    const float* Ws_seen = (const float*)d_in[7];
    const float* bs_seen = (const float*)d_in[8];
    const float* Wd_seen = (const float*)d_in[9];
    const float* bd_seen = (const float*)d_in[10];
    const float* attn_seen = (const float*)d_in[11];
    const float* Wr_seen = (const float*)d_in[12];
    const float* br_seen = (const float*)d_in[13];
    const float* Ws_near = (const float*)d_in[14];
    const float* bs_near = (const float*)d_in[15];
    const float* Wd_near = (const float*)d_in[16];
    const float* bd_near = (const float*)d_in[17];
    const float* attn_near = (const float*)d_in[18];
    const float* Wr_near = (const float*)d_in[19];
    const float* br_near = (const float*)d_in[20];
    const float* W_aggr  = (const float*)d_in[21];
    const float* b_aggr  = (const float*)d_in[22];
    float* out = (float*)d_out;

    int n_gt  = in_sizes[0] / 8;
    int n_ubs = in_sizes[1] / 8;
    int n_ag  = in_sizes[2] / 16;
    int e_seen = in_sizes[3];
    int e_near = in_sizes[5];

    // side stream + fork/join events (host-side objects, created once;
    // no device memory is allocated here)
    static cudaStream_t s2 = nullptr;
    static cudaEvent_t evFork = nullptr, evJoin = nullptr;
    if (!s2) {
        cudaStreamCreateWithFlags(&s2, cudaStreamNonBlocking);
        cudaEventCreateWithFlags(&evFork, cudaEventDisableTiming);
        cudaEventCreateWithFlags(&evJoin, cudaEventDisableTiming);
    }

    // fork: CSR chain (independent of projections) runs on s2
    cudaEventRecord(evFork, 0);
    cudaStreamWaitEvent(s2, evFork, 0);

    k_zero<<<(2 * NAG + 255) / 256, 256, 0, s2>>>();
    k_hist<<<dim3(256, 2), 256, 0, s2>>>(seen_dst, e_seen, near_dst, e_near);
    k_assign<<<(2 * n_ag + 255) / 256, 256, 0, s2>>>(n_ag);
    k_scatter<<<dim3(256, 2), 256, 0, s2>>>(seen_dst, seen_src, e_seen,
                                            near_dst, near_src, e_near);
    cudaEventRecord(evJoin, s2);

    // projections on the main stream, concurrent with the CSR chain
    int pbx = (n_gt + 127) / 128;
    k_proj_all<<<dim3(pbx, 6), 256>>>(x_gt, x_ubs, x_ag,
        Ws_seen, bs_seen, Ws_near, bs_near,
        Wd_seen, bd_seen, Wr_seen, br_seen,
        Wd_near, bd_near, Wr_near, br_near,
        n_gt, n_ubs, n_ag);

    // join: gat needs both g_feat and the CSR
    cudaStreamWaitEvent(0, evJoin, 0);

    k_gat<<<dim3((n_ag + 7) / 8, 2), 256>>>(attn_seen, attn_near, n_ag);

    k_gemm<<<dim3(HID / 128, (n_ag + 63) / 64), 256>>>(W_aggr, b_aggr, out, n_ag);
}

// round 12
// speedup vs baseline: 1.5356x; 1.2748x over previous
#include <cuda_runtime.h>
#include <cuda_bf16.h>

#define H 4
#define Dh 64
#define HID 256
#define NGT 100000
#define NUBS 20000
#define NAG 20000
#define ESEEN 320000
#define ENEAR 160000

typedef unsigned long long u64;
typedef unsigned int u32;

__device__ __forceinline__ u64 pk2(float lo, float hi) {
    u64 r; asm("mov.b64 %0,{%1,%2};" : "=l"(r) : "f"(lo), "f"(hi)); return r;
}
__device__ __forceinline__ u64 f2fma(u64 a, u64 b, u64 c) {
    u64 d; asm("fma.rn.f32x2 %0,%1,%2,%3;" : "=l"(d) : "l"(a), "l"(b), "l"(c)); return d;
}

// bf16 hi/lo split helpers
__device__ __forceinline__ void bfsplit(float v, unsigned short& h, unsigned short& l) {
    __nv_bfloat16 hb = __float2bfloat16_rn(v);
    h = __bfloat16_as_ushort(hb);
    float r = v - __bfloat162float(hb);
    l = __bfloat16_as_ushort(__float2bfloat16_rn(r));
}

__device__ __forceinline__ void mma_bf16(float* d, const u32* a, u32 b0, u32 b1) {
    asm volatile(
        "mma.sync.aligned.m16n8k16.row.col.f32.bf16.bf16.f32 "
        "{%0,%1,%2,%3},{%4,%5,%6,%7},{%8,%9},{%0,%1,%2,%3};"
        : "+f"(d[0]), "+f"(d[1]), "+f"(d[2]), "+f"(d[3])
        : "r"(a[0]), "r"(a[1]), "r"(a[2]), "r"(a[3]), "r"(b0), "r"(b1));
}

// ---------------- scratch (device globals, no runtime alloc) ----------------
__device__ float g_feat[(NGT + NUBS + 4 * NAG) * HID];
__device__ u32   g_xh[NAG * 256];         // xcat hi: bf16x2 pairs, [row][256]
__device__ u32   g_xl[NAG * 256];         // xcat lo
__device__ uint2 g_wfh[32 * 256 * 4];     // W_aggr hi, mma-B-fragment layout [ks][n][tg]
__device__ uint2 g_wfl[32 * 256 * 4];     // W_aggr lo
__device__ int   g_cnt[2 * NAG];
__device__ int   g_cur[2 * NAG];
__device__ int   g_off[2 * NAG];
__device__ int   g_base[2];
__device__ int   g_perm[ESEEN + ENEAR];

#define FS_SEEN 0L
#define FS_NEAR ((long)NGT * HID)
#define FD_S    ((long)(NGT + NUBS) * HID)
#define RES_S   (FD_S + (long)NAG * HID)
#define FD_N    (RES_S + (long)NAG * HID)
#define RES_N   (FD_N + (long)NAG * HID)

__global__ void k_zero() {
    int i = blockIdx.x * blockDim.x + threadIdx.x;
    if (i < 2 * NAG) g_cnt[i] = 0;
    if (i < 2) g_base[i] = 0;
}

// ---------------- W_aggr -> bf16 hi/lo in B-fragment layout ----------------
// b0 packs W[k0][n],W[k0+1][n]; b1 packs W[k0+8][n],W[k0+9][n]; k0 = ks*16+tg*2
__global__ void k_wprep(const float* __restrict__ W) {
    int t = blockIdx.x * 256 + threadIdx.x;
    if (t >= 32 * 256 * 4) return;
    int ks = t >> 10, rem = t & 1023;
    int n = rem >> 2, tg = rem & 3;
    int k0 = ks * 16 + tg * 2;
    float v0 = W[(k0 + 0) * HID + n], v1 = W[(k0 + 1) * HID + n];
    float v2 = W[(k0 + 8) * HID + n], v3 = W[(k0 + 9) * HID + n];
    unsigned short h0, l0, h1, l1, h2, l2, h3, l3;
    bfsplit(v0, h0, l0); bfsplit(v1, h1, l1);
    bfsplit(v2, h2, l2); bfsplit(v3, h3, l3);
    g_wfh[t] = make_uint2((u32)h0 | ((u32)h1 << 16), (u32)h2 | ((u32)h3 << 16));
    g_wfl[t] = make_uint2((u32)l0 | ((u32)l1 << 16), (u32)l2 | ((u32)l3 << 16));
}

// ---------------- fused projections ----------------
template<int F>
__device__ __forceinline__ void proj_body(const float* __restrict__ x,
                                          const float* __restrict__ W,
                                          const float* __restrict__ b,
                                          int n, long out_off) {
    int node0 = blockIdx.x * 128;
    if (node0 >= n) return;
    __shared__ float sx[128 * 16];
    int cnt = n - node0; if (cnt > 128) cnt = 128;
    int nf4 = (cnt * F) >> 2;
    for (int i = threadIdx.x; i < nf4; i += 256)
        *(float4*)(sx + i * 4) = *(const float4*)(x + (long)node0 * F + i * 4);
    __syncthreads();

    int warp = threadIdx.x >> 5, lane = threadIdx.x & 31;
    int c = (warp & 3) * 64 + (lane << 1);
    int nh = (warp >> 2) * 64;
    u64 wp[F];
#pragma unroll
    for (int k = 0; k < F; k++) wp[k] = *(const u64*)(W + k * HID + c);
    u64 bp = *(const u64*)(b + c);

    int jend = nh + 64; if (jend > cnt) jend = cnt;
#pragma unroll 1
    for (int j = nh; j < jend; j++) {
        const float* xr = sx + j * F;
        u64 acc = bp;
#pragma unroll
        for (int k4 = 0; k4 < F; k4 += 4) {
            float4 xv = *(const float4*)(xr + k4);
            acc = f2fma(pk2(xv.x, xv.x), wp[k4 + 0], acc);
            acc = f2fma(pk2(xv.y, xv.y), wp[k4 + 1], acc);
            acc = f2fma(pk2(xv.z, xv.z), wp[k4 + 2], acc);
            acc = f2fma(pk2(xv.w, xv.w), wp[k4 + 3], acc);
        }
        *(u64*)(g_feat + out_off + (long)(node0 + j) * HID + c) = acc;
    }
}

__global__ void k_proj_all(const float* xg, const float* xu, const float* xa,
                           const float* Wsg, const float* bsg,
                           const float* Wsu, const float* bsu,
                           const float* W0, const float* b0,
                           const float* W1, const float* b1,
                           const float* W2, const float* b2,
                           const float* W3, const float* b3,
                           int n_gt, int n_ubs, int n_ag) {
    switch (blockIdx.y) {
        case 0: proj_body<8>(xg, Wsg, bsg, n_gt, FS_SEEN); break;
        case 1: proj_body<8>(xu, Wsu, bsu, n_ubs, FS_NEAR); break;
        case 2: proj_body<16>(xa, W0, b0, n_ag, FD_S);  break;
        case 3: proj_body<16>(xa, W1, b1, n_ag, RES_S); break;
        case 4: proj_body<16>(xa, W2, b2, n_ag, FD_N);  break;
        default: proj_body<16>(xa, W3, b3, n_ag, RES_N); break;
    }
}

// ---------------- CSR build ----------------
__global__ void k_hist(const int* __restrict__ dA, int eA,
                       const int* __restrict__ dB, int eB) {
    int g = blockIdx.y;
    const int* dst = g ? dB : dA;
    int e = g ? eB : eA;
    int co = g ? NAG : 0;
    for (int i = blockIdx.x * blockDim.x + threadIdx.x; i < e;
         i += gridDim.x * blockDim.x)
        atomicAdd(&g_cnt[co + __ldg(dst + i)], 1);
}

__global__ void k_assign(int n) {
    int i = blockIdx.x * blockDim.x + threadIdx.x;
    if (i >= 2 * n) return;
    int g = (i >= n) ? 1 : 0;
    int lane = threadIdx.x & 31;
    int c = g_cnt[i];
    int pre = c;
#pragma unroll
    for (int o = 1; o < 32; o <<= 1) {
        int v = __shfl_up_sync(0xffffffffu, pre, o);
        if (lane >= o) pre += v;
    }
    int total = __shfl_sync(0xffffffffu, pre, 31);
    int excl = pre - c;
    int base = 0;
    if (lane == 31) base = atomicAdd(&g_base[g], total);
    base = __shfl_sync(0xffffffffu, base, 31);
    g_off[i] = base + excl;
    g_cur[i] = base + excl;
}

__global__ void k_scatter(const int* __restrict__ dA, const int* __restrict__ sA, int eA,
                          const int* __restrict__ dB, const int* __restrict__ sB, int eB) {
    int g = blockIdx.y;
    const int* dst = g ? dB : dA;
    const int* src = g ? sB : sA;
    int e = g ? eB : eA;
    int pb = g ? ESEEN : 0;
    for (int i = blockIdx.x * blockDim.x + threadIdx.x; i < e;
         i += gridDim.x * blockDim.x) {
        int p = atomicAdd(&g_cur[g * NAG + __ldg(dst + i)], 1);
        g_perm[pb + p] = __ldg(src + i);
    }
}

// ---------------- GATv2: one warp per dst, all 4 heads; chunk-of-4 ----------------
__device__ __forceinline__ float lrelu(float v) { return (v >= 0.f) ? v : 0.2f * v; }

__device__ __forceinline__ float escore(float4 fa, float4 fb, float4 d0, float4 d1,
                                        float4 a0, float4 a1) {
    float p;
    p = lrelu(fa.x + d0.x) * a0.x;
    p = fmaf(lrelu(fa.y + d0.y), a0.y, p);
    p = fmaf(lrelu(fa.z + d0.z), a0.z, p);
    p = fmaf(lrelu(fa.w + d0.w), a0.w, p);
    p = fmaf(lrelu(fb.x + d1.x), a1.x, p);
    p = fmaf(lrelu(fb.y + d1.y), a1.y, p);
    p = fmaf(lrelu(fb.z + d1.z), a1.z, p);
    p = fmaf(lrelu(fb.w + d1.w), a1.w, p);
    return p;
}

__global__ void __launch_bounds__(256) k_gat(const float* __restrict__ attnS,
                                             const float* __restrict__ attnN, int nag) {
    int g = blockIdx.y;
    const float* attn = g ? attnN : attnS;
    long fs_off  = g ? FS_NEAR : FS_SEEN;
    long fd_off  = g ? FD_N    : FD_S;
    long res_off = g ? RES_N   : RES_S;
    int gbase    = g ? NAG : 0;
    int pb       = g ? ESEEN : 0;
    int xoff     = g ? HID : 0;

    int warp = threadIdx.x >> 5, lane = threadIdx.x & 31;
    int dstn = blockIdx.x * 8 + warp;
    if (dstn >= nag) return;
    int off = lane * 8;

    float4 a0 = __ldg((const float4*)(attn + off));
    float4 a1 = __ldg((const float4*)(attn + off + 4));
    const float* fdr = g_feat + fd_off + (long)dstn * HID + off;
    float4 d0 = *(const float4*)(fdr);
    float4 d1 = *(const float4*)(fdr + 4);
    const float* rvr = g_feat + res_off + (long)dstn * HID + off;
    float4 r0 = *(const float4*)(rvr);
    float4 r1 = *(const float4*)(rvr + 4);

    int e0 = g_off[gbase + dstn];
    int e1 = e0 + g_cnt[gbase + dstn];
    const float* fs = g_feat + fs_off;
    const int* pp = g_perm + pb;

    int id0 = 0, id1 = 0, id2 = 0, id3 = 0;
    if (e0 < e1) {
        int rr = e1 - e0;
        id0 = pp[e0];
        id1 = (rr > 1) ? pp[e0 + 1] : id0;
        id2 = (rr > 2) ? pp[e0 + 2] : id0;
        id3 = (rr > 3) ? pp[e0 + 3] : id0;
    }

    float mx = -3.0e38f, den = 0.f;
    float4 acc0 = make_float4(0.f, 0.f, 0.f, 0.f), acc1 = acc0;

    for (int i = e0; i < e1; i += 4) {
        const float* p0r = fs + (long)id0 * HID + off;
        const float* p1r = fs + (long)id1 * HID + off;
        const float* p2r = fs + (long)id2 * HID + off;
        const float* p3r = fs + (long)id3 * HID + off;
        float4 f0a = __ldg((const float4*)p0r), f0b = __ldg((const float4*)(p0r + 4));
        float4 f1a = __ldg((const float4*)p1r), f1b = __ldg((const float4*)(p1r + 4));
        float4 f2a = __ldg((const float4*)p2r), f2b = __ldg((const float4*)(p2r + 4));
        float4 f3a = __ldg((const float4*)p3r), f3b = __ldg((const float4*)(p3r + 4));

        if (i + 4 < e1) {
            int j = i + 4, rr = e1 - j;
            id0 = pp[j];
            id1 = (rr > 1) ? pp[j + 1] : id0;
            id2 = (rr > 2) ? pp[j + 2] : id0;
            id3 = (rr > 3) ? pp[j + 3] : id0;
        }

        float p0 = escore(f0a, f0b, d0, d1, a0, a1);
        float p1 = escore(f1a, f1b, d0, d1, a0, a1);
        float p2 = escore(f2a, f2b, d0, d1, a0, a1);
        float p3 = escore(f3a, f3b, d0, d1, a0, a1);
#pragma unroll
        for (int o = 1; o < 8; o <<= 1) {
            p0 += __shfl_xor_sync(0xffffffffu, p0, o);
            p1 += __shfl_xor_sync(0xffffffffu, p1, o);
            p2 += __shfl_xor_sync(0xffffffffu, p2, o);
            p3 += __shfl_xor_sync(0xffffffffu, p3, o);
        }
        int r = e1 - i;
        if (r < 2) p1 = -3.0e38f;
        if (r < 3) p2 = -3.0e38f;
        if (r < 4) p3 = -3.0e38f;

        float cm = fmaxf(fmaxf(p0, p1), fmaxf(p2, p3));
        float nmx = fmaxf(mx, cm);
        float scale = __expf(mx - nmx);
        float x0 = __expf(p0 - nmx);
        float x1 = __expf(p1 - nmx);
        float x2 = __expf(p2 - nmx);
        float x3 = __expf(p3 - nmx);
        den = fmaf(den, scale, (x0 + x1) + (x2 + x3));
        acc0.x = fmaf(acc0.x, scale, fmaf(x0, f0a.x, fmaf(x1, f1a.x, fmaf(x2, f2a.x, x3 * f3a.x))));
        acc0.y = fmaf(acc0.y, scale, fmaf(x0, f0a.y, fmaf(x1, f1a.y, fmaf(x2, f2a.y, x3 * f3a.y))));
        acc0.z = fmaf(acc0.z, scale, fmaf(x0, f0a.z, fmaf(x1, f1a.z, fmaf(x2, f2a.z, x3 * f3a.z))));
        acc0.w = fmaf(acc0.w, scale, fmaf(x0, f0a.w, fmaf(x1, f1a.w, fmaf(x2, f2a.w, x3 * f3a.w))));
        acc1.x = fmaf(acc1.x, scale, fmaf(x0, f0b.x, fmaf(x1, f1b.x, fmaf(x2, f2b.x, x3 * f3b.x))));
        acc1.y = fmaf(acc1.y, scale, fmaf(x0, f0b.y, fmaf(x1, f1b.y, fmaf(x2, f2b.y, x3 * f3b.y))));
        acc1.z = fmaf(acc1.z, scale, fmaf(x0, f0b.z, fmaf(x1, f1b.z, fmaf(x2, f2b.z, x3 * f3b.z))));
        acc1.w = fmaf(acc1.w, scale, fmaf(x0, f0b.w, fmaf(x1, f1b.w, fmaf(x2, f2b.w, x3 * f3b.w))));
        mx = nmx;
    }
    float inv = (e1 == e0) ? 1.f : (1.f / den);
    float o[8];
    o[0] = fmaxf(fmaf(acc0.x, inv, r0.x), 0.f);
    o[1] = fmaxf(fmaf(acc0.y, inv, r0.y), 0.f);
    o[2] = fmaxf(fmaf(acc0.z, inv, r0.z), 0.f);
    o[3] = fmaxf(fmaf(acc0.w, inv, r0.w), 0.f);
    o[4] = fmaxf(fmaf(acc1.x, inv, r1.x), 0.f);
    o[5] = fmaxf(fmaf(acc1.y, inv, r1.y), 0.f);
    o[6] = fmaxf(fmaf(acc1.z, inv, r1.z), 0.f);
    o[7] = fmaxf(fmaf(acc1.w, inv, r1.w), 0.f);
    // write bf16 hi/lo packed pairs (even k in low half)
    u32 hp[4], lp[4];
#pragma unroll
    for (int j = 0; j < 4; j++) {
        unsigned short h0, l0, h1, l1;
        bfsplit(o[2 * j], h0, l0);
        bfsplit(o[2 * j + 1], h1, l1);
        hp[j] = (u32)h0 | ((u32)h1 << 16);
        lp[j] = (u32)l0 | ((u32)l1 << 16);
    }
    int pidx = dstn * 256 + (xoff >> 1) + lane * 4;
    *(uint4*)(g_xh + pidx) = make_uint4(hp[0], hp[1], hp[2], hp[3]);
    *(uint4*)(g_xl + pidx) = make_uint4(lp[0], lp[1], lp[2], lp[3]);
}

// ---------------- final GEMM via split-bf16 mma.sync ----------------
// out = relu(xcat[M,512] @ W[512,256] + b); D = Ahi*Bhi + Ahi*Blo + Alo*Bhi
// block 128Mx128N, 8 warps (4x2), each warp 32Mx64N of m16n8k16 tiles.
__global__ void __launch_bounds__(256) k_gemm(const float* __restrict__ bias,
                                              float* __restrict__ C, int M) {
    const int N = HID;
    int warp = threadIdx.x >> 5, lane = threadIdx.x & 31;
    int g = lane >> 2, tg = lane & 3;
    int bm = blockIdx.y * 128, bn = blockIdx.x * 128;
    int wm = (warp >> 1) * 32, wn = (warp & 1) * 64;

    float acc[2][8][4];
#pragma unroll
    for (int mt = 0; mt < 2; mt++)
#pragma unroll
        for (int nt = 0; nt < 8; nt++)
#pragma unroll
            for (int q = 0; q < 4; q++) acc[mt][nt][q] = 0.f;

#pragma unroll 1
    for (int ks = 0; ks < 32; ks++) {
        u32 ah[2][4], al[2][4];
        int pb = ks * 8 + tg;
#pragma unroll
        for (int mt = 0; mt < 2; mt++) {
            int r0 = bm + wm + mt * 16 + g;
            int r1 = r0 + 8;
            if (r0 > M - 1) r0 = M - 1;
            if (r1 > M - 1) r1 = M - 1;
            ah[mt][0] = g_xh[r0 * 256 + pb];
            ah[mt][1] = g_xh[r1 * 256 + pb];
            ah[mt][2] = g_xh[r0 * 256 + pb + 4];
            ah[mt][3] = g_xh[r1 * 256 + pb + 4];
            al[mt][0] = g_xl[r0 * 256 + pb];
            al[mt][1] = g_xl[r1 * 256 + pb];
            al[mt][2] = g_xl[r0 * 256 + pb + 4];
            al[mt][3] = g_xl[r1 * 256 + pb + 4];
        }
        const uint2* wh = g_wfh + (ks * 256 + bn + wn) * 4 + lane;
        const uint2* wl = g_wfl + (ks * 256 + bn + wn) * 4 + lane;
#pragma unroll
        for (int nt = 0; nt < 8; nt++) {
            uint2 bh = __ldg(wh + nt * 32);
            uint2 bl = __ldg(wl + nt * 32);
#pragma unroll
            for (int mt = 0; mt < 2; mt++) {
                mma_bf16(acc[mt][nt], ah[mt], bh.x, bh.y);
                mma_bf16(acc[mt][nt], ah[mt], bl.x, bl.y);
                mma_bf16(acc[mt][nt], al[mt], bh.x, bh.y);
            }
        }
    }

#pragma unroll
    for (int mt = 0; mt < 2; mt++) {
        int r0 = bm + wm + mt * 16 + g;
        int r1 = r0 + 8;
#pragma unroll
        for (int nt = 0; nt < 8; nt++) {
            int n0 = bn + wn + nt * 8 + tg * 2;
            float b0f = bias[n0], b1f = bias[n0 + 1];
            if (r0 < M) {
                float2 v;
                v.x = fmaxf(acc[mt][nt][0] + b0f, 0.f);
                v.y = fmaxf(acc[mt][nt][1] + b1f, 0.f);
                *(float2*)(C + (long)r0 * N + n0) = v;
            }
            if (r1 < M) {
                float2 v;
                v.x = fmaxf(acc[mt][nt][2] + b0f, 0.f);
                v.y = fmaxf(acc[mt][nt][3] + b1f, 0.f);
                *(float2*)(C + (long)r1 * N + n0) = v;
            }
        }
    }
}

// ---------------- launch ----------------
extern "C" void kernel_launch(void* const* d_in, const int* in_sizes, int n_in,
                              void* d_out, int out_size) {
    const float* x_gt   = (const float*)d_in[0];
    const float* x_ubs  = (const float*)d_in[1];
    const float* x_ag   = (const float*)d_in[2];
    const int* seen_src = (const int*)d_in[3];
    const int* seen_dst = (const int*)d_in[4];
    const int* near_src = (const int*)d_in[5];
    const int* near_dst = (const int*)d_in[6];
    const float* Ws_seen = (const float*)d_in[7];
    const float* bs_seen = (const float*)d_in[8];
    const float* Wd_seen = (const float*)d_in[9];
    const float* bd_seen = (const float*)d_in[10];
    const float* attn_seen = (const float*)d_in[11];
    const float* Wr_seen = (const float*)d_in[12];
    const float* br_seen = (const float*)d_in[13];
    const float* Ws_near = (const float*)d_in[14];
    const float* bs_near = (const float*)d_in[15];
    const float* Wd_near = (const float*)d_in[16];
    const float* bd_near = (const float*)d_in[17];
    const float* attn_near = (const float*)d_in[18];
    const float* Wr_near = (const float*)d_in[19];
    const float* br_near = (const float*)d_in[20];
    const float* W_aggr  = (const float*)d_in[21];
    const float* b_aggr  = (const float*)d_in[22];
    float* out = (float*)d_out;

    int n_gt  = in_sizes[0] / 8;
    int n_ubs = in_sizes[1] / 8;
    int n_ag  = in_sizes[2] / 16;
    int e_seen = in_sizes[3];
    int e_near = in_sizes[5];

    static cudaStream_t s2 = nullptr;
    static cudaEvent_t evFork = nullptr, evJoin = nullptr;
    if (!s2) {
        cudaStreamCreateWithFlags(&s2, cudaStreamNonBlocking);
        cudaEventCreateWithFlags(&evFork, cudaEventDisableTiming);
        cudaEventCreateWithFlags(&evJoin, cudaEventDisableTiming);
    }

    // fork: CSR chain + W prep (independent of projections) on s2
    cudaEventRecord(evFork, 0);
    cudaStreamWaitEvent(s2, evFork, 0);

    k_wprep<<<128, 256, 0, s2>>>(W_aggr);
    k_zero<<<(2 * NAG + 255) / 256, 256, 0, s2>>>();
    k_hist<<<dim3(256, 2), 256, 0, s2>>>(seen_dst, e_seen, near_dst, e_near);
    k_assign<<<(2 * n_ag + 255) / 256, 256, 0, s2>>>(n_ag);
    k_scatter<<<dim3(256, 2), 256, 0, s2>>>(seen_dst, seen_src, e_seen,
                                            near_dst, near_src, e_near);
    cudaEventRecord(evJoin, s2);

    // projections on the main stream, concurrent with s2
    int pbx = (n_gt + 127) / 128;
    k_proj_all<<<dim3(pbx, 6), 256>>>(x_gt, x_ubs, x_ag,
        Ws_seen, bs_seen, Ws_near, bs_near,
        Wd_seen, bd_seen, Wr_seen, br_seen,
        Wd_near, bd_near, Wr_near, br_near,
        n_gt, n_ubs, n_ag);

    cudaStreamWaitEvent(0, evJoin, 0);

    k_gat<<<dim3((n_ag + 7) / 8, 2), 256>>>(attn_seen, attn_near, n_ag);

    k_gemm<<<dim3(HID / 128, (n_ag + 127) / 128), 256>>>(b_aggr, out, n_ag);
}